// round 3
// baseline (speedup 1.0000x reference)
#include <cuda_runtime.h>
#include <math.h>

// DistanceTransformLoss: BCE-with-logits mean + sqrt(border) where
// border = sum(pred_bin * dist) / count_nonzero and
// dist[i] = min(H, |i - nearest target row in column|)   (exact identity of
// the two-pass grassfire transform with init=H).
//
// Shapes: predictions/targets (32, 1, 1024, 1024) float32. Output: 1 float.

#define HH 1024
#define WW 1024
#define NELEM (32ull * 1024ull * 1024ull)
#define DINF (1 << 20)

// Accumulators. Zero at module load; final kernel resets them after reading,
// so every launch / graph replay starts from zero. Deterministic.
__device__ double g_bce;
__device__ double g_total;
__device__ unsigned long long g_count;

// Block = 1024 threads = 32 warps; 32 consecutive columns x full H=1024 of
// one image. lane -> column (coalesced 128B warp loads), warp -> 32-row
// chunk, chunk state packed to a 32-bit mask per thread.
//
// Phase 1 (all global traffic): load t[j],p[j] pairs, accumulate BCE, pack
//   target mask m and prediction mask pb. 64 independent loads -> deep MLP,
//   no later reloads.
// Phase 2 (ALU only): cross-warp min-plus carries via warp-shuffle prefix /
//   suffix min scans (transposed through padded smem), then per-element
//   distance from masks by clz/ffs bit tricks. Penalty sum + count.
__global__ __launch_bounds__(1024, 2)
void dtl_main_kernel(const float* __restrict__ pred,
                     const float* __restrict__ tgt) {
    __shared__ int sA[32][33];   // [chunk][column], padded: conflict-free transpose
    __shared__ int sB[32][33];
    __shared__ float sBce[32];
    __shared__ float sTot[32];
    __shared__ int   sCnt[32];

    const int lane = threadIdx.x & 31;
    const int w    = threadIdx.x >> 5;
    const int n     = blockIdx.x >> 5;          // image (32 blocks/image)
    const int cbase = (blockIdx.x & 31) << 5;   // column group base
    const int col   = cbase + lane;

    const size_t base = (size_t)n * HH * WW + (size_t)(w << 5) * WW + col;
    const float* tp = tgt + base;
    const float* pp = pred + base;

    // ---- Phase 1: single fused load pass (targets + predictions) ----
    unsigned m = 0u;    // target bitmask, bit j = row (32w + j)
    unsigned pb = 0u;   // prediction>0 bitmask
    float bce = 0.0f;
    #pragma unroll
    for (int j = 0; j < 32; j++) {
        float t = __ldcs(tp + (size_t)j * WW);
        float p = __ldcs(pp + (size_t)j * WW);
        m  |= (t == 1.0f ? 1u : 0u) << j;
        pb |= (p > 0.0f  ? 1u : 0u) << j;
        float ax = fabsf(p);
        bce += fmaxf(p, 0.0f) - p * t + __logf(1.0f + __expf(-ax));
    }

    // Chunk summaries:
    //  A = dist from next chunk's row 0 up to this chunk's last 1
    //  B = dist from prev chunk's row 31 down to this chunk's first 1
    sA[w][lane] = m ? (__clz(m) + 1) : DINF;
    sB[w][lane] = m ? __ffs(m)       : DINF;
    __syncthreads();

    // ---- Phase 2a: cross-warp carries via shuffle scans ----
    // Warp w owns column w; lane v holds chunk v's summary.
    // U[chunk]  = min_{v<chunk}(A_v + 32*(chunk-1-v)) = exclPrefixMin(A_v-32v) + 32*(chunk-1)
    // Dn[chunk] = min_{v>chunk}(B_v + 32*(v-1-chunk)) = exclSuffixMin(B_v+32v) - 32*(chunk+1)
    {
        int a = sA[lane][w] - 32 * lane;
        #pragma unroll
        for (int o = 1; o < 32; o <<= 1) {
            int x = __shfl_up_sync(0xffffffffu, a, o);
            if (lane >= o) a = min(a, x);
        }
        int ea = __shfl_up_sync(0xffffffffu, a, 1);
        if (lane == 0) ea = DINF;
        int Uv = ea + 32 * (lane - 1);

        int b = sB[lane][w] + 32 * lane;
        #pragma unroll
        for (int o = 1; o < 32; o <<= 1) {
            int x = __shfl_down_sync(0xffffffffu, b, o);
            if (lane < 32 - o) b = min(b, x);
        }
        int eb = __shfl_down_sync(0xffffffffu, b, 1);
        if (lane == 31) eb = DINF;
        int Dv = eb - 32 * (lane + 1);

        // Each thread overwrites exactly the slot it read: no hazard.
        sA[lane][w] = Uv;
        sB[lane][w] = Dv;
    }
    __syncthreads();
    const int U  = sA[w][lane];  // dist from this chunk's row 0 to nearest 1 above
    const int Dn = sB[w][lane];  // dist from this chunk's row 31 to nearest 1 below

    // ---- Phase 2b: penalty from masks (no memory) ----
    float tot = 0.0f;
    int cnt = 0;
    #pragma unroll
    for (int j = 0; j < 32; j++) {
        if ((pb >> j) & 1u) {
            unsigned mlow  = m << (31 - j);
            unsigned mhigh = m >> j;
            int dup   = mlow  ? __clz(mlow)        : U + j;
            int ddown = mhigh ? (__ffs(mhigh) - 1) : Dn + (31 - j);
            int d = min(min(dup, ddown), HH);
            tot += (float)d;
            cnt += (d != 0) ? 1 : 0;
        }
    }

    // ---- Reduce: warp shfl -> smem -> warp0 shfl -> global double atomics ----
    #pragma unroll
    for (int o = 16; o > 0; o >>= 1) {
        bce += __shfl_xor_sync(0xffffffffu, bce, o);
        tot += __shfl_xor_sync(0xffffffffu, tot, o);
        cnt += __shfl_xor_sync(0xffffffffu, cnt, o);
    }
    if (lane == 0) {
        sBce[w] = bce;
        sTot[w] = tot;
        sCnt[w] = cnt;
    }
    __syncthreads();
    if (w == 0) {
        float b  = sBce[lane];
        float tt = sTot[lane];
        int   c  = sCnt[lane];
        #pragma unroll
        for (int o = 16; o > 0; o >>= 1) {
            b  += __shfl_xor_sync(0xffffffffu, b, o);
            tt += __shfl_xor_sync(0xffffffffu, tt, o);
            c  += __shfl_xor_sync(0xffffffffu, c, o);
        }
        if (lane == 0) {
            atomicAdd(&g_bce, (double)b);
            atomicAdd(&g_total, (double)tt);
            atomicAdd(&g_count, (unsigned long long)c);
        }
    }
}

__global__ void dtl_final_kernel(float* __restrict__ out) {
    double bce_mean = g_bce / (double)NELEM;
    double total = g_total;
    double cnt = (double)g_count;
    double border = (total == 0.0) ? 0.0 : total / fmax(cnt, 1.0);
    out[0] = (float)(bce_mean + sqrt(border));
    // Reset for next invocation / graph replay (entry invariant: all zero).
    g_bce = 0.0;
    g_total = 0.0;
    g_count = 0ull;
}

extern "C" void kernel_launch(void* const* d_in, const int* in_sizes, int n_in,
                              void* d_out, int out_size) {
    const float* pred = (const float*)d_in[0];
    const float* tgt  = (const float*)d_in[1];
    float* out = (float*)d_out;

    // 32768 columns total / 32 columns per block = 1024 blocks
    dtl_main_kernel<<<1024, 1024>>>(pred, tgt);
    dtl_final_kernel<<<1, 1>>>(out);
}

// round 4
// speedup vs baseline: 1.2110x; 1.2110x over previous
#include <cuda_runtime.h>
#include <math.h>

// DistanceTransformLoss: BCE-with-logits mean + sqrt(border) where
// border = sum(pred_bin * dist) / count_nonzero and
// dist[i] = min(H, |i - nearest target row in column|)   (exact identity of
// the two-pass grassfire transform with init=H).
//
// Shapes: predictions/targets (32, 1, 1024, 1024) float32. Output: 1 float.

#define HH 1024
#define WW 1024
#define NELEM (32ull * 1024ull * 1024ull)
#define DINF (1 << 20)

// Accumulators. Zero at module load; final kernel resets them after reading,
// so every launch / graph replay starts from zero. Deterministic.
__device__ double g_bce;
__device__ double g_total;
__device__ unsigned long long g_count;

// Block = 1024 threads = 32 warps; 32 consecutive columns x full H=1024 of
// one image. lane -> column (coalesced 128B warp loads), warp -> 32-row
// chunk, chunk state packed into a 32-bit mask per thread.
//
// All 64 global loads (targets then predictions) issue BEFORE the only
// barrier, in two low-register loops so ptxas batches them deeply. The
// barrier-exposed tail is pure ALU (~350 instrs).
__global__ __launch_bounds__(1024, 1)
void dtl_main_kernel(const float* __restrict__ pred,
                     const float* __restrict__ tgt) {
    __shared__ int sA[32][33];   // [chunk][column], padded for transpose
    __shared__ int sB[32][33];
    __shared__ float sBce[32];
    __shared__ float sTot[32];
    __shared__ int   sCnt[32];

    const int lane = threadIdx.x & 31;
    const int w    = threadIdx.x >> 5;
    const int n     = blockIdx.x >> 5;          // image (32 blocks/image)
    const int cbase = (blockIdx.x & 31) << 5;   // column group base
    const int col   = cbase + lane;

    const size_t base = (size_t)n * HH * WW + (size_t)(w << 5) * WW + col;
    const float* tp = tgt + base;
    const float* pp = pred + base;

    // ---- Load loop 1: targets -> bitmask (32 independent loads) ----
    unsigned m = 0u;    // target bitmask, bit j = row (32w + j)
    #pragma unroll
    for (int j = 0; j < 32; j++) {
        float t = __ldcs(tp + (size_t)j * WW);
        m |= (t == 1.0f ? 1u : 0u) << j;
    }

    // Chunk summaries (no barrier yet):
    //  A = dist from next chunk's row 0 up to this chunk's last 1
    //  B = dist from prev chunk's row 31 down to this chunk's first 1
    sA[w][lane] = m ? (__clz(m) + 1) : DINF;
    sB[w][lane] = m ? __ffs(m)       : DINF;

    // ---- Load loop 2: predictions -> BCE + pb mask (32 independent loads) ----
    unsigned pb = 0u;   // prediction>0 bitmask
    float bce = 0.0f;
    #pragma unroll
    for (int j = 0; j < 32; j++) {
        float p = __ldcs(pp + (size_t)j * WW);
        pb |= (p > 0.0f ? 1u : 0u) << j;
        float t = (float)((m >> j) & 1u);
        float ax = fabsf(p);
        bce += fmaxf(p, 0.0f) - p * t + __logf(1.0f + __expf(-ax));
    }

    __syncthreads();

    // ---- Cross-warp carries via shuffle min-scans (transposed) ----
    // Warp w owns column w; lane v holds chunk v's summary.
    // U[c]  = min_{v<c}(A_v + 32*(c-1-v)) = exclPrefixMin(A_v-32v) + 32*(c-1)
    // Dn[c] = min_{v>c}(B_v + 32*(v-1-c)) = exclSuffixMin(B_v+32v) - 32*(c+1)
    {
        int a = sA[lane][w] - 32 * lane;
        #pragma unroll
        for (int o = 1; o < 32; o <<= 1) {
            int x = __shfl_up_sync(0xffffffffu, a, o);
            if (lane >= o) a = min(a, x);
        }
        int ea = __shfl_up_sync(0xffffffffu, a, 1);
        if (lane == 0) ea = DINF;
        int Uv = ea + 32 * (lane - 1);

        int b = sB[lane][w] + 32 * lane;
        #pragma unroll
        for (int o = 1; o < 32; o <<= 1) {
            int x = __shfl_down_sync(0xffffffffu, b, o);
            if (lane < 32 - o) b = min(b, x);
        }
        int eb = __shfl_down_sync(0xffffffffu, b, 1);
        if (lane == 31) eb = DINF;
        int Dv = eb - 32 * (lane + 1);

        // Each thread overwrites exactly the slot it read: no hazard.
        sA[lane][w] = Uv;
        sB[lane][w] = Dv;
    }
    __syncthreads();
    const int U  = sA[w][lane];  // dist from this chunk's row 0 to nearest 1 above
    const int Dn = sB[w][lane];  // dist from this chunk's row 31 to nearest 1 below

    // ---- Penalty from masks (ALU only) ----
    // penalty != 0  <=>  pred>0 and dist!=0  <=>  bit of (pb & ~m)
    const unsigned q = pb & ~m;
    int cnt = __popc(q);
    float tot = 0.0f;
    #pragma unroll
    for (int j = 0; j < 32; j++) {
        if ((q >> j) & 1u) {
            unsigned mlow  = m << (31 - j);
            unsigned mhigh = m >> j;
            int dup   = mlow  ? __clz(mlow)        : U + j;
            int ddown = mhigh ? (__ffs(mhigh) - 1) : Dn + (31 - j);
            tot += (float)min(min(dup, ddown), HH);
        }
    }

    // ---- Reduce: warp shfl -> smem -> warp0 shfl -> global double atomics ----
    #pragma unroll
    for (int o = 16; o > 0; o >>= 1) {
        bce += __shfl_xor_sync(0xffffffffu, bce, o);
        tot += __shfl_xor_sync(0xffffffffu, tot, o);
        cnt += __shfl_xor_sync(0xffffffffu, cnt, o);
    }
    if (lane == 0) {
        sBce[w] = bce;
        sTot[w] = tot;
        sCnt[w] = cnt;
    }
    __syncthreads();
    if (w == 0) {
        float b  = sBce[lane];
        float tt = sTot[lane];
        int   c  = sCnt[lane];
        #pragma unroll
        for (int o = 16; o > 0; o >>= 1) {
            b  += __shfl_xor_sync(0xffffffffu, b, o);
            tt += __shfl_xor_sync(0xffffffffu, tt, o);
            c  += __shfl_xor_sync(0xffffffffu, c, o);
        }
        if (lane == 0) {
            atomicAdd(&g_bce, (double)b);
            atomicAdd(&g_total, (double)tt);
            atomicAdd(&g_count, (unsigned long long)c);
        }
    }
}

__global__ void dtl_final_kernel(float* __restrict__ out) {
    double bce_mean = g_bce / (double)NELEM;
    double total = g_total;
    double cnt = (double)g_count;
    double border = (total == 0.0) ? 0.0 : total / fmax(cnt, 1.0);
    out[0] = (float)(bce_mean + sqrt(border));
    // Reset for next invocation / graph replay (entry invariant: all zero).
    g_bce = 0.0;
    g_total = 0.0;
    g_count = 0ull;
}

extern "C" void kernel_launch(void* const* d_in, const int* in_sizes, int n_in,
                              void* d_out, int out_size) {
    const float* pred = (const float*)d_in[0];
    const float* tgt  = (const float*)d_in[1];
    float* out = (float*)d_out;

    // 32768 columns total / 32 columns per block = 1024 blocks
    dtl_main_kernel<<<1024, 1024>>>(pred, tgt);
    dtl_final_kernel<<<1, 1>>>(out);
}

// round 5
// speedup vs baseline: 1.5018x; 1.2401x over previous
#include <cuda_runtime.h>
#include <math.h>

// DistanceTransformLoss: BCE-with-logits mean + sqrt(border) where
// border = sum(pred_bin * dist) / count_nonzero and
// dist[i] = min(H, |i - nearest target row in column|)   (exact identity of
// the two-pass grassfire transform with init=H).
//
// Shapes: predictions/targets (32, 1, 1024, 1024) float32. Output: 1 float.

#define HH 1024
#define WW 1024
#define NELEM (32ull * 1024ull * 1024ull)
#define DINF (1 << 20)

// Accumulators. Zero at module load; final kernel resets them after reading,
// so every launch / graph replay starts from zero. Deterministic.
__device__ double g_bce;
__device__ double g_total;
__device__ unsigned long long g_count;

// 256 blocks x 1024 threads. Block: image n = b>>3, 128-column group cg = b&7.
// warp w -> rows 32w..32w+31; lane l -> 4 consecutive columns via float4
// (warp row-load = 512B contiguous). Each thread: 4 column masks. float4
// keeps 4x bytes in flight per outstanding load -> covers DRAM latency.
// Column c of a thread maps to carry-tile index (l + 32c): transpose write
// (stride 33, conflict-free) and shuffle-scan reads both clean.
__global__ __launch_bounds__(1024, 1)
void dtl_main_kernel(const float* __restrict__ pred,
                     const float* __restrict__ tgt) {
    __shared__ int sA[128][33];   // [column][chunk]
    __shared__ int sB[128][33];
    __shared__ float sBce[32];
    __shared__ float sTot[32];
    __shared__ int   sCnt[32];

    const int lane = threadIdx.x & 31;
    const int w    = threadIdx.x >> 5;
    const int n    = blockIdx.x >> 3;
    const int cg   = blockIdx.x & 7;

    const size_t base = (size_t)n * HH * WW + (size_t)(w << 5) * WW
                      + (size_t)(cg << 7) + (size_t)(lane << 2);
    const float4* tp4 = (const float4*)(tgt + base);
    const float4* pp4 = (const float4*)(pred + base);

    // ---- Load loop 1: targets -> 4 bitmasks ----
    unsigned m[4] = {0u, 0u, 0u, 0u};
    #pragma unroll
    for (int j = 0; j < 32; j++) {
        float4 t4 = __ldcs(tp4 + j * (WW / 4));
        m[0] |= (t4.x == 1.0f ? 1u : 0u) << j;
        m[1] |= (t4.y == 1.0f ? 1u : 0u) << j;
        m[2] |= (t4.z == 1.0f ? 1u : 0u) << j;
        m[3] |= (t4.w == 1.0f ? 1u : 0u) << j;
    }

    // Chunk summaries (no barrier yet):
    //  A = dist from next chunk's row 0 up to this chunk's last 1
    //  B = dist from prev chunk's row 31 down to this chunk's first 1
    #pragma unroll
    for (int c = 0; c < 4; c++) {
        sA[lane + 32 * c][w] = m[c] ? (__clz(m[c]) + 1) : DINF;
        sB[lane + 32 * c][w] = m[c] ? __ffs(m[c])       : DINF;
    }

    // ---- Load loop 2: predictions -> BCE + pb masks ----
    unsigned pb[4] = {0u, 0u, 0u, 0u};
    float bce0 = 0.0f, bce1 = 0.0f;
    #pragma unroll
    for (int j = 0; j < 32; j++) {
        float4 p4 = __ldcs(pp4 + j * (WW / 4));
        {
            float p = p4.x; pb[0] |= (p > 0.0f ? 1u : 0u) << j;
            float t = (float)((m[0] >> j) & 1u);
            bce0 += fmaxf(p, 0.0f) - p * t + __logf(1.0f + __expf(-fabsf(p)));
        }
        {
            float p = p4.y; pb[1] |= (p > 0.0f ? 1u : 0u) << j;
            float t = (float)((m[1] >> j) & 1u);
            bce1 += fmaxf(p, 0.0f) - p * t + __logf(1.0f + __expf(-fabsf(p)));
        }
        {
            float p = p4.z; pb[2] |= (p > 0.0f ? 1u : 0u) << j;
            float t = (float)((m[2] >> j) & 1u);
            bce0 += fmaxf(p, 0.0f) - p * t + __logf(1.0f + __expf(-fabsf(p)));
        }
        {
            float p = p4.w; pb[3] |= (p > 0.0f ? 1u : 0u) << j;
            float t = (float)((m[3] >> j) & 1u);
            bce1 += fmaxf(p, 0.0f) - p * t + __logf(1.0f + __expf(-fabsf(p)));
        }
    }
    float bce = bce0 + bce1;

    __syncthreads();

    // ---- Cross-warp carries: warp w scans columns w+32c (shuffle min-scans) ----
    // U[ch]  = min_{v<ch}(A_v + 32*(ch-1-v)) = exclPrefixMin(A_v-32v) + 32*(ch-1)
    // Dn[ch] = min_{v>ch}(B_v + 32*(v-1-ch)) = exclSuffixMin(B_v+32v) - 32*(ch+1)
    #pragma unroll
    for (int c = 0; c < 4; c++) {
        const int k = w + 32 * c;
        int a = sA[k][lane] - 32 * lane;
        #pragma unroll
        for (int o = 1; o < 32; o <<= 1) {
            int x = __shfl_up_sync(0xffffffffu, a, o);
            if (lane >= o) a = min(a, x);
        }
        int ea = __shfl_up_sync(0xffffffffu, a, 1);
        if (lane == 0) ea = DINF;

        int b = sB[k][lane] + 32 * lane;
        #pragma unroll
        for (int o = 1; o < 32; o <<= 1) {
            int x = __shfl_down_sync(0xffffffffu, b, o);
            if (lane < 32 - o) b = min(b, x);
        }
        int eb = __shfl_down_sync(0xffffffffu, b, 1);
        if (lane == 31) eb = DINF;

        sA[k][lane] = ea + 32 * (lane - 1);   // U for chunk=lane, column k
        sB[k][lane] = eb - 32 * (lane + 1);   // Dn
    }
    __syncthreads();

    // ---- Penalty: sparse iteration over set bits of q = pb & ~m ----
    // penalty != 0  <=>  pred>0 and dist!=0  <=>  bit of q
    float tot = 0.0f;
    int cnt = 0;
    #pragma unroll
    for (int c = 0; c < 4; c++) {
        const int U  = sA[lane + 32 * c][w];
        const int Dn = sB[lane + 32 * c][w];
        unsigned q = pb[c] & ~m[c];
        const unsigned mc = m[c];
        cnt += __popc(q);
        while (q) {
            int j = __ffs(q) - 1;
            q &= q - 1u;
            unsigned mlow  = mc << (31 - j);
            unsigned mhigh = mc >> j;
            int dup   = mlow  ? __clz(mlow)        : U + j;
            int ddown = mhigh ? (__ffs(mhigh) - 1) : Dn + (31 - j);
            tot += (float)min(min(dup, ddown), HH);
        }
    }

    // ---- Reduce: warp shfl -> smem -> warp0 shfl -> global double atomics ----
    #pragma unroll
    for (int o = 16; o > 0; o >>= 1) {
        bce += __shfl_xor_sync(0xffffffffu, bce, o);
        tot += __shfl_xor_sync(0xffffffffu, tot, o);
        cnt += __shfl_xor_sync(0xffffffffu, cnt, o);
    }
    if (lane == 0) {
        sBce[w] = bce;
        sTot[w] = tot;
        sCnt[w] = cnt;
    }
    __syncthreads();
    if (w == 0) {
        float b  = sBce[lane];
        float tt = sTot[lane];
        int   c  = sCnt[lane];
        #pragma unroll
        for (int o = 16; o > 0; o >>= 1) {
            b  += __shfl_xor_sync(0xffffffffu, b, o);
            tt += __shfl_xor_sync(0xffffffffu, tt, o);
            c  += __shfl_xor_sync(0xffffffffu, c, o);
        }
        if (lane == 0) {
            atomicAdd(&g_bce, (double)b);
            atomicAdd(&g_total, (double)tt);
            atomicAdd(&g_count, (unsigned long long)c);
        }
    }
}

__global__ void dtl_final_kernel(float* __restrict__ out) {
    double bce_mean = g_bce / (double)NELEM;
    double total = g_total;
    double cnt = (double)g_count;
    double border = (total == 0.0) ? 0.0 : total / fmax(cnt, 1.0);
    out[0] = (float)(bce_mean + sqrt(border));
    // Reset for next invocation / graph replay (entry invariant: all zero).
    g_bce = 0.0;
    g_total = 0.0;
    g_count = 0ull;
}

extern "C" void kernel_launch(void* const* d_in, const int* in_sizes, int n_in,
                              void* d_out, int out_size) {
    const float* pred = (const float*)d_in[0];
    const float* tgt  = (const float*)d_in[1];
    float* out = (float*)d_out;

    // 32 images x 8 column-groups of 128 columns = 256 blocks
    dtl_main_kernel<<<256, 1024>>>(pred, tgt);
    dtl_final_kernel<<<1, 1>>>(out);
}